// round 16
// baseline (speedup 1.0000x reference)
#include <cuda_runtime.h>
#include <cuda_bf16.h>
#include <cstdint>

// ---------------------------------------------------------------------------
// GraphSageWithSampling — GB300 sm_103a via warp-level mma.sync bf16 (HMMA).
// tcgen05 is unavailable: harness compiles through compute_103 (no 'a'),
// where all tcgen05/.cta_group features are rejected by ptxas (R7 evidence).
// 3-term bf16 hi/lo split keeps rel_err ~1e-5.
// FS=128, DF=64, L = [1024000, 204800, 40960, 8192], FAN=5.
// ---------------------------------------------------------------------------

#define FS 128
#define DF 64
#define L0N 1024000
#define L1N 204800
#define L2N 40960
#define L3N 8192

__device__ float g_hs0[(size_t)L0N * FS];
__device__ float g_hs1[(size_t)L1N * FS];
__device__ float g_hs2[(size_t)L2N * FS];
__device__ float g_hs3[(size_t)L3N * FS];

// m16n8k16 row.col bf16 -> fp32 accumulate (supported since sm_80).
__device__ __forceinline__ void mma16816(float* c, const uint32_t* a,
                                         uint32_t b0, uint32_t b1) {
    asm volatile(
        "mma.sync.aligned.m16n8k16.row.col.f32.bf16.bf16.f32 "
        "{%0,%1,%2,%3}, {%4,%5,%6,%7}, {%8,%9}, {%0,%1,%2,%3};"
        : "+f"(c[0]), "+f"(c[1]), "+f"(c[2]), "+f"(c[3])
        : "r"(a[0]), "r"(a[1]), "r"(a[2]), "r"(a[3]), "r"(b0), "r"(b1));
}

// bf16 hi/lo split of a float pair -> packed bf16x2 words.
__device__ __forceinline__ void split2(float a, float b, uint32_t& hi, uint32_t& lo) {
    __nv_bfloat162 h = __floats2bfloat162_rn(a, b);
    float ra = a - __bfloat162float(h.x);
    float rb = b - __bfloat162float(h.y);
    __nv_bfloat162 l = __floats2bfloat162_rn(ra, rb);
    hi = *reinterpret_cast<uint32_t*>(&h);
    lo = *reinterpret_cast<uint32_t*>(&l);
}

__device__ __forceinline__ float lrelu(float x) { return x > 0.f ? x : 0.01f * x; }

// Padded row strides in 32-bit words. stride mod 32 == 4 makes the fragment
// load pattern (g in 0..7, t in 0..3 -> word g*stride + t) touch 32 distinct
// banks: (4g + t) covers 0..31.
#define KPW 36    // K=64 bf16 row: 32 data words + 4 pad
#define XPW 132   // K=256 bf16 row: 128 data words + 4 pad

// ---------------------------------------------------------------------------
// proj: hs[n] = emb[nid[n]+1] + lrelu(f[n] @ Wp^T + bp).
// Block: 256 threads (8 warps), 128 nodes. Warp w owns rows 16w..16w+15.
// SMEM words: sAh/sAl [128*36], sBh/sBl [128*36]  = 73728 B.
// ---------------------------------------------------------------------------
#define SMEM_PROJ (4 * 128 * KPW * 4)

__global__ __launch_bounds__(256) void proj_mma_kernel(
    const float* __restrict__ f, const int* __restrict__ nid,
    const float* __restrict__ emb, const float* __restrict__ Wp,
    const float* __restrict__ bp, float* __restrict__ hs)
{
    extern __shared__ uint32_t sm[];
    uint32_t* sAh = sm;
    uint32_t* sAl = sAh + 128 * KPW;
    uint32_t* sBh = sAl + 128 * KPW;
    uint32_t* sBl = sBh + 128 * KPW;

    const int tid = threadIdx.x, wid = tid >> 5, lane = tid & 31;
    const int g = lane >> 2, t = lane & 3;
    const int r = tid >> 1, hf = tid & 1;          // stage row, k-half
    const size_t base = (size_t)blockIdx.x * 128;

    // Stage A (f tile) and B (Wp) as hi/lo bf16, padded row-major.
    {
        const float4* fp = reinterpret_cast<const float4*>(f + (base + r) * DF + hf * 32);
        const float4* wp = reinterpret_cast<const float4*>(Wp + (size_t)r * DF + hf * 32);
#pragma unroll
        for (int i = 0; i < 8; ++i) {
            float4 v = fp[i];
            uint32_t h0, l0, h1, l1;
            split2(v.x, v.y, h0, l0);
            split2(v.z, v.w, h1, l1);
            int w = r * KPW + hf * 16 + 2 * i;
            *reinterpret_cast<uint2*>(&sAh[w]) = make_uint2(h0, h1);
            *reinterpret_cast<uint2*>(&sAl[w]) = make_uint2(l0, l1);
            v = wp[i];
            split2(v.x, v.y, h0, l0);
            split2(v.z, v.w, h1, l1);
            *reinterpret_cast<uint2*>(&sBh[w]) = make_uint2(h0, h1);
            *reinterpret_cast<uint2*>(&sBl[w]) = make_uint2(l0, l1);
        }
    }
    __syncthreads();

    // MMA: acc[j] covers n-tile j (cols 8j..8j+7), rows 16*wid..+15.
    float acc[16][4];
#pragma unroll
    for (int j = 0; j < 16; ++j)
        acc[j][0] = acc[j][1] = acc[j][2] = acc[j][3] = 0.f;

    const int m0 = wid * 16;
    for (int ks = 0; ks < 4; ++ks) {
        const int aw = (m0 + g) * KPW + ks * 8 + t;
        const int aw8 = (m0 + g + 8) * KPW + ks * 8 + t;
        uint32_t aH[4] = {sAh[aw], sAh[aw8], sAh[aw + 4], sAh[aw8 + 4]};
        uint32_t aL[4] = {sAl[aw], sAl[aw8], sAl[aw + 4], sAl[aw8 + 4]};
#pragma unroll
        for (int j = 0; j < 16; ++j) {
            const int bw = (j * 8 + g) * KPW + ks * 8 + t;
            uint32_t b0h = sBh[bw], b1h = sBh[bw + 4];
            uint32_t b0l = sBl[bw], b1l = sBl[bw + 4];
            mma16816(acc[j], aH, b0h, b1h);
            mma16816(acc[j], aH, b0l, b1l);
            mma16816(acc[j], aL, b0h, b1h);
        }
    }

    // Epilogue: lane owns rows (m0+g, m0+g+8), cols 8j+2t, 8j+2t+1.
    const int n0 = (int)base + m0 + g;
    const int n1 = n0 + 8;
    const int node0 = __ldg(&nid[n0]);
    const int node1 = __ldg(&nid[n1]);
    const float* e0 = emb + (size_t)(node0 + 1) * FS;
    const float* e1 = emb + (size_t)(node1 + 1) * FS;
#pragma unroll
    for (int j = 0; j < 16; ++j) {
        const int c = 8 * j + 2 * t;
        float2 bb = *reinterpret_cast<const float2*>(&bp[c]);
        float2 ev0 = *reinterpret_cast<const float2*>(&e0[c]);
        float2 ev1 = *reinterpret_cast<const float2*>(&e1[c]);
        float2 z0, z1;
        z0.x = lrelu(acc[j][0] + bb.x) + ev0.x;
        z0.y = lrelu(acc[j][1] + bb.y) + ev0.y;
        z1.x = lrelu(acc[j][2] + bb.x) + ev1.x;
        z1.y = lrelu(acc[j][3] + bb.y) + ev1.y;
        *reinterpret_cast<float2*>(&hs[(size_t)n0 * FS + c]) = z0;
        *reinterpret_cast<float2*>(&hs[(size_t)n1 * FS + c]) = z1;
    }
}

// ---------------------------------------------------------------------------
// sage: one GraphSAGE layer.
//   X = [h | (sum5(src) - h)/4]  (K=256), Z = X @ W^T + b, (lrelu), row-norm.
// Block: 256 threads (8 warps), 128 dsts. X staged once (hi/lo); W chunk
// (K=64) restaged per kc with __syncthreads fencing.
// SMEM words: sXh/sXl [128*132] + sBh/sBl [128*36] = 172032 B (1 CTA/SM).
// ---------------------------------------------------------------------------
#define SMEM_SAGE ((2 * 128 * XPW + 2 * 128 * KPW) * 4)

__global__ __launch_bounds__(256) void sage_mma_kernel(
    const float* __restrict__ hs_in, const float* __restrict__ hs_own,
    const int* __restrict__ src, const float* __restrict__ W,
    const float* __restrict__ b, float* __restrict__ out, int do_lrelu)
{
    extern __shared__ uint32_t sm[];
    uint32_t* sXh = sm;
    uint32_t* sXl = sXh + 128 * XPW;
    uint32_t* sBh = sXl + 128 * XPW;
    uint32_t* sBl = sBh + 128 * KPW;

    const int tid = threadIdx.x, wid = tid >> 5, lane = tid & 31;
    const int g = lane >> 2, t = lane & 3;
    const int r = tid >> 1, hf = tid & 1;          // stage row, ch-half
    const size_t dBase = (size_t)blockIdx.x * 128;
    const int d = (int)dBase + r;
    const int c0 = hf * 64;

    // ---- Phase 1: gather + build X hi/lo ----
    {
        int sidx[5];
#pragma unroll
        for (int j = 0; j < 5; ++j) sidx[j] = __ldg(&src[(size_t)d * 5 + j]);
        const float4* hp = reinterpret_cast<const float4*>(hs_own + (size_t)d * FS + c0);
#pragma unroll
        for (int gq = 0; gq < 4; ++gq) {           // groups of 4 float4
            float4 h4[4], s4[4];
#pragma unroll
            for (int i = 0; i < 4; ++i) {
                h4[i] = hp[4 * gq + i];
                s4[i] = make_float4(0.f, 0.f, 0.f, 0.f);
            }
#pragma unroll
            for (int j = 0; j < 5; ++j) {
                const float4* vp = reinterpret_cast<const float4*>(
                    hs_in + (size_t)sidx[j] * FS + c0);
#pragma unroll
                for (int i = 0; i < 4; ++i) {
                    float4 v = vp[4 * gq + i];
                    s4[i].x += v.x; s4[i].y += v.y; s4[i].z += v.z; s4[i].w += v.w;
                }
            }
#pragma unroll
            for (int i = 0; i < 4; ++i) {
                const int cc = c0 + 16 * gq + 4 * i;     // channel within h-part
                const int w = r * XPW + cc / 2;          // h at word cc/2
                uint32_t h0, l0, h1, l1;
                split2(h4[i].x, h4[i].y, h0, l0);
                split2(h4[i].z, h4[i].w, h1, l1);
                *reinterpret_cast<uint2*>(&sXh[w]) = make_uint2(h0, h1);
                *reinterpret_cast<uint2*>(&sXl[w]) = make_uint2(l0, l1);
                float4 a;
                a.x = (s4[i].x - h4[i].x) * 0.25f;
                a.y = (s4[i].y - h4[i].y) * 0.25f;
                a.z = (s4[i].z - h4[i].z) * 0.25f;
                a.w = (s4[i].w - h4[i].w) * 0.25f;
                split2(a.x, a.y, h0, l0);
                split2(a.z, a.w, h1, l1);
                *reinterpret_cast<uint2*>(&sXh[w + 64]) = make_uint2(h0, h1);  // agg at +128 ch
                *reinterpret_cast<uint2*>(&sXl[w + 64]) = make_uint2(l0, l1);
            }
        }
    }

    // ---- Phase 2: K=256 in 4 chunks; W chunk restaged per kc ----
    float acc[16][4];
#pragma unroll
    for (int j = 0; j < 16; ++j)
        acc[j][0] = acc[j][1] = acc[j][2] = acc[j][3] = 0.f;

    const int m0 = wid * 16;
    for (int kc = 0; kc < 4; ++kc) {
        __syncthreads();   // kc=0: X ready; kc>0: all warps done with prev B
        {
            const float4* wp = reinterpret_cast<const float4*>(
                W + (size_t)r * 256 + kc * 64 + hf * 32);
#pragma unroll
            for (int i = 0; i < 8; ++i) {
                float4 v = wp[i];
                uint32_t h0, l0, h1, l1;
                split2(v.x, v.y, h0, l0);
                split2(v.z, v.w, h1, l1);
                int w = r * KPW + hf * 16 + 2 * i;
                *reinterpret_cast<uint2*>(&sBh[w]) = make_uint2(h0, h1);
                *reinterpret_cast<uint2*>(&sBl[w]) = make_uint2(l0, l1);
            }
        }
        __syncthreads();

        for (int ks = 0; ks < 4; ++ks) {
            const int kw = kc * 32 + ks * 8 + t;   // word offset within X row
            const int aw = (m0 + g) * XPW + kw;
            const int aw8 = (m0 + g + 8) * XPW + kw;
            uint32_t aH[4] = {sXh[aw], sXh[aw8], sXh[aw + 4], sXh[aw8 + 4]};
            uint32_t aL[4] = {sXl[aw], sXl[aw8], sXl[aw + 4], sXl[aw8 + 4]};
#pragma unroll
            for (int j = 0; j < 16; ++j) {
                const int bw = (j * 8 + g) * KPW + ks * 8 + t;
                uint32_t b0h = sBh[bw], b1h = sBh[bw + 4];
                uint32_t b0l = sBl[bw], b1l = sBl[bw + 4];
                mma16816(acc[j], aH, b0h, b1h);
                mma16816(acc[j], aH, b0l, b1l);
                mma16816(acc[j], aL, b0h, b1h);
            }
        }
    }

    // ---- Epilogue: bias (+lrelu), warp-local row L2-norm, store ----
    float ss0 = 0.f, ss1 = 0.f;
#pragma unroll
    for (int j = 0; j < 16; ++j) {
        const int c = 8 * j + 2 * t;
        float2 bb = *reinterpret_cast<const float2*>(&b[c]);
        float v0 = acc[j][0] + bb.x, v1 = acc[j][1] + bb.y;
        float v2 = acc[j][2] + bb.x, v3 = acc[j][3] + bb.y;
        if (do_lrelu) {
            v0 = lrelu(v0); v1 = lrelu(v1); v2 = lrelu(v2); v3 = lrelu(v3);
        }
        acc[j][0] = v0; acc[j][1] = v1; acc[j][2] = v2; acc[j][3] = v3;
        ss0 += v0 * v0 + v1 * v1;
        ss1 += v2 * v2 + v3 * v3;
    }
    // Row lives in the 4 lanes sharing g (t = 0..3 are lane bits 0-1).
    ss0 += __shfl_xor_sync(0xffffffffu, ss0, 1);
    ss0 += __shfl_xor_sync(0xffffffffu, ss0, 2);
    ss1 += __shfl_xor_sync(0xffffffffu, ss1, 1);
    ss1 += __shfl_xor_sync(0xffffffffu, ss1, 2);
    const float inv0 = 1.0f / fmaxf(sqrtf(ss0), 1e-6f);
    const float inv1 = 1.0f / fmaxf(sqrtf(ss1), 1e-6f);

    const int r0 = (int)dBase + m0 + g;
    const int r1 = r0 + 8;
#pragma unroll
    for (int j = 0; j < 16; ++j) {
        const int c = 8 * j + 2 * t;
        *reinterpret_cast<float2*>(&out[(size_t)r0 * FS + c]) =
            make_float2(acc[j][0] * inv0, acc[j][1] * inv0);
        *reinterpret_cast<float2*>(&out[(size_t)r1 * FS + c]) =
            make_float2(acc[j][2] * inv1, acc[j][3] * inv1);
    }
}

// ---------------------------------------------------------------------------
// Launcher — 7 kernels, graph-capturable, allocation-free.
// Interleaved (dict) order: 9:f0 10:nid0 11:f1 12:nid1 13:f2 14:nid2 15:f3
// 16:nid3 17:dst0 18:src0 19:dst1 20:src1 21:dst2 22:src2; disambiguated via
// in_sizes[10] (nid0 = 1,024,000 elems).  dst arrays unused (repeat(arange,5)).
// ---------------------------------------------------------------------------
extern "C" void kernel_launch(void* const* d_in, const int* in_sizes, int n_in,
                              void* d_out, int out_size)
{
    const float* node_emb = (const float*)d_in[0];
    const float* Wp = (const float*)d_in[1];
    const float* bp = (const float*)d_in[2];
    const float* W0 = (const float*)d_in[3];
    const float* b0 = (const float*)d_in[4];
    const float* W1 = (const float*)d_in[5];
    const float* b1 = (const float*)d_in[6];
    const float* W2 = (const float*)d_in[7];
    const float* b2 = (const float*)d_in[8];

    const float *f0, *f1, *f2, *f3;
    const int *nid0, *nid1, *nid2, *nid3, *src0, *src1, *src2;

    if (in_sizes[10] == L0N) {
        f0 = (const float*)d_in[9];  nid0 = (const int*)d_in[10];
        f1 = (const float*)d_in[11]; nid1 = (const int*)d_in[12];
        f2 = (const float*)d_in[13]; nid2 = (const int*)d_in[14];
        f3 = (const float*)d_in[15]; nid3 = (const int*)d_in[16];
        src0 = (const int*)d_in[18];
        src1 = (const int*)d_in[20];
        src2 = (const int*)d_in[22];
    } else {
        f0 = (const float*)d_in[9];  f1 = (const float*)d_in[10];
        f2 = (const float*)d_in[11]; f3 = (const float*)d_in[12];
        nid0 = (const int*)d_in[13]; nid1 = (const int*)d_in[14];
        nid2 = (const int*)d_in[15]; nid3 = (const int*)d_in[16];
        src0 = (const int*)d_in[17]; src1 = (const int*)d_in[18];
        src2 = (const int*)d_in[19];
    }
    float* out = (float*)d_out;

    float *hs0, *hs1, *hs2, *hs3;
    cudaGetSymbolAddress((void**)&hs0, g_hs0);
    cudaGetSymbolAddress((void**)&hs1, g_hs1);
    cudaGetSymbolAddress((void**)&hs2, g_hs2);
    cudaGetSymbolAddress((void**)&hs3, g_hs3);

    cudaFuncSetAttribute(proj_mma_kernel,
                         cudaFuncAttributeMaxDynamicSharedMemorySize, SMEM_PROJ);
    cudaFuncSetAttribute(sage_mma_kernel,
                         cudaFuncAttributeMaxDynamicSharedMemorySize, SMEM_SAGE);

    proj_mma_kernel<<<L0N / 128, 256, SMEM_PROJ>>>(f0, nid0, node_emb, Wp, bp, hs0);
    proj_mma_kernel<<<L1N / 128, 256, SMEM_PROJ>>>(f1, nid1, node_emb, Wp, bp, hs1);
    proj_mma_kernel<<<L2N / 128, 256, SMEM_PROJ>>>(f2, nid2, node_emb, Wp, bp, hs2);
    proj_mma_kernel<<<L3N / 128, 256, SMEM_PROJ>>>(f3, nid3, node_emb, Wp, bp, hs3);

    sage_mma_kernel<<<L1N / 128, 256, SMEM_SAGE>>>(hs0, hs1, src0, W0, b0, hs1, 1);
    sage_mma_kernel<<<L2N / 128, 256, SMEM_SAGE>>>(hs1, hs2, src1, W1, b1, hs2, 1);
    sage_mma_kernel<<<L3N / 128, 256, SMEM_SAGE>>>(hs2, hs3, src2, W2, b2, out, 0);
}